// round 1
// baseline (speedup 1.0000x reference)
#include <cuda_runtime.h>

#define NATOMS   1500
#define NODE_DIM 128
#define HIDDEN   64
#define MUL1E    64
#define HID1E    32
#define NUM_BASIS 20

// Per-node packed data: a[3], b[3], coord[3], pad[3]  (48B, float4-aligned)
__device__ float g_node[NATOMS * 12];

__global__ void node_kernel(
    const float* __restrict__ xs,   const float* __restrict__ xsph,
    const float* __restrict__ coord,
    const float* __restrict__ Wsi1, const float* __restrict__ Wsi2,
    const float* __restrict__ Wsj1, const float* __restrict__ Wsj2,
    const float* __restrict__ Wpi1, const float* __restrict__ Wpi2,
    const float* __restrict__ Wpj1, const float* __restrict__ Wpj2)
{
    int n = blockIdx.x;
    int t = threadIdx.x;
    __shared__ float sx[NODE_DIM];
    __shared__ float sv[MUL1E * 3];
    __shared__ float red[128];
    __shared__ float shp[MUL1E * 3];
    __shared__ float sres[2];

    sx[t] = xs[n * NODE_DIM + t];
    const float* vp = xsph + n * 480 + 128;   // 1e block [64,3]
    for (int k = t; k < MUL1E * 3; k += 128) sv[k] = vp[k];
    __syncthreads();

    // ---- scalar MLPs: silu(x@W1)@W2.  threads 0..63 -> i-role, 64..127 -> j-role
    {
        const float* W1 = (t < 64) ? Wsi1 : Wsj1;
        const float* W2 = (t < 64) ? Wsi2 : Wsj2;
        int h = t & 63;
        float d = 0.f;
        #pragma unroll 8
        for (int f = 0; f < NODE_DIM; f++) d += sx[f] * W1[f * HIDDEN + h];
        float s = d / (1.f + __expf(-d));     // silu
        red[t] = s * W2[h];
    }

    // ---- spherical MLPs: threads 0..31 -> i-role, 32..63 -> j-role
    if (t < 64) {
        const float* W1 = (t < 32) ? Wpi1 : Wpj1;
        const float* W2 = (t < 32) ? Wpi2 : Wpj2;
        int h = t & 31;
        float h0 = 0.f, h1 = 0.f, h2 = 0.f;
        #pragma unroll 8
        for (int m = 0; m < MUL1E; m++) {
            float w = W1[m * HID1E + h];
            h0 += sv[m * 3 + 0] * w;
            h1 += sv[m * 3 + 1] * w;
            h2 += sv[m * 3 + 2] * w;
        }
        h0 *= 0.125f; h1 *= 0.125f; h2 *= 0.125f;   // / sqrt(64)
        float nrm = sqrtf(h0 * h0 + h1 * h1 + h2 * h2);
        float gate = 1.f / (1.f + __expf(-nrm));    // sigmoid(|h|)
        float w2 = W2[h] * gate;
        shp[t * 3 + 0] = h0 * w2;
        shp[t * 3 + 1] = h1 * w2;
        shp[t * 3 + 2] = h2 * w2;
    }
    __syncthreads();

    if (t == 0)  { float s = 0.f; for (int h = 0;  h < 64;  h++) s += red[h]; sres[0] = s; }
    if (t == 64) { float s = 0.f; for (int h = 64; h < 128; h++) s += red[h]; sres[1] = s; }
    __syncthreads();

    if (t == 0) {
        float oi[3] = {0, 0, 0}, oj[3] = {0, 0, 0};
        for (int h = 0;  h < 32; h++) { oi[0] += shp[h*3+0]; oi[1] += shp[h*3+1]; oi[2] += shp[h*3+2]; }
        for (int h = 32; h < 64; h++) { oj[0] += shp[h*3+0]; oj[1] += shp[h*3+1]; oj[2] += shp[h*3+2]; }
        const float inv32 = 0.17677669529663689f;   // 1/sqrt(32)
        float fa = 1.f + sres[0];
        float fb = 1.f + sres[1];
        float* gp = g_node + n * 12;
        // e3nn (y,z,x) -> (x,y,z) permutation [2,0,1], fold in gate (1+s)
        gp[0] = oi[2] * inv32 * fa;  gp[1] = oi[0] * inv32 * fa;  gp[2] = oi[1] * inv32 * fa;
        gp[3] = oj[2] * inv32 * fb;  gp[4] = oj[0] * inv32 * fb;  gp[5] = oj[1] * inv32 * fb;
        gp[6] = coord[n*3+0];  gp[7] = coord[n*3+1];  gp[8] = coord[n*3+2];
        gp[9] = 0.f; gp[10] = 0.f; gp[11] = 0.f;
    }
}

// out[(i*N+j), p, q] = 0.5 * fc(d_ij) * (a_i[p]*b_j[q] + b_i[p]*a_j[q])
__global__ void edge_kernel(const float* __restrict__ Wrbf, float* __restrict__ out)
{
    int i = blockIdx.y;
    int j = blockIdx.x * blockDim.x + threadIdx.x;

    __shared__ float sW[NUM_BASIS];
    __shared__ float si[9];
    if (threadIdx.x < NUM_BASIS) sW[threadIdx.x] = Wrbf[threadIdx.x];
    if (threadIdx.x < 9)         si[threadIdx.x] = g_node[i * 12 + threadIdx.x];
    __syncthreads();
    if (j >= NATOMS) return;

    const float4* np = (const float4*)(g_node + j * 12);
    float4 n0 = np[0], n1 = np[1], n2 = np[2];
    float aj0 = n0.x, aj1 = n0.y, aj2 = n0.z;
    float bj0 = n0.w, bj1 = n1.x, bj2 = n1.y;

    float dx = si[6] - n1.z, dy = si[7] - n1.w, dz = si[8] - n2.x;
    float d = sqrtf(dx * dx + dy * dy + dz * dz);

    const float delta = 5.0f / 19.0f;
    const float coeff = -0.5f / (delta * delta);
    float fc = 0.f;
    #pragma unroll
    for (int k = 0; k < NUM_BASIS; k++) {
        float u = d - (float)k * delta;
        fc += sW[k] * __expf(coeff * u * u);
    }
    float h = 0.5f * fc;

    float ai0 = si[0] * h, ai1 = si[1] * h, ai2 = si[2] * h;
    float bi0 = si[3] * h, bi1 = si[4] * h, bi2 = si[5] * h;

    float* o = out + ((size_t)i * NATOMS + j) * 9;
    o[0] = ai0 * bj0 + bi0 * aj0;
    o[1] = ai0 * bj1 + bi0 * aj1;
    o[2] = ai0 * bj2 + bi0 * aj2;
    o[3] = ai1 * bj0 + bi1 * aj0;
    o[4] = ai1 * bj1 + bi1 * aj1;
    o[5] = ai1 * bj2 + bi1 * aj2;
    o[6] = ai2 * bj0 + bi2 * aj0;
    o[7] = ai2 * bj1 + bi2 * aj1;
    o[8] = ai2 * bj2 + bi2 * aj2;
}

extern "C" void kernel_launch(void* const* d_in, const int* in_sizes, int n_in,
                              void* d_out, int out_size)
{
    const float* xs    = (const float*)d_in[0];
    const float* xsph  = (const float*)d_in[1];
    const float* coord = (const float*)d_in[2];
    // d_in[3] = fc_edge_index (int32, full graph i-major) — structure is fixed, not needed
    const float* Wsi1 = (const float*)d_in[4];
    const float* Wsi2 = (const float*)d_in[5];
    const float* Wsj1 = (const float*)d_in[6];
    const float* Wsj2 = (const float*)d_in[7];
    const float* Wpi1 = (const float*)d_in[8];
    const float* Wpi2 = (const float*)d_in[9];
    const float* Wpj1 = (const float*)d_in[10];
    const float* Wpj2 = (const float*)d_in[11];
    const float* Wrbf = (const float*)d_in[12];
    float* out = (float*)d_out;

    node_kernel<<<NATOMS, 128>>>(xs, xsph, coord,
                                 Wsi1, Wsi2, Wsj1, Wsj2,
                                 Wpi1, Wpi2, Wpj1, Wpj2);

    dim3 grid((NATOMS + 255) / 256, NATOMS);
    edge_kernel<<<grid, 256>>>(Wrbf, out);
}

// round 3
// speedup vs baseline: 1.4973x; 1.4973x over previous
#include <cuda_runtime.h>

#define NATOMS   1500
#define NODE_DIM 128
#define HIDDEN   64
#define MUL1E    64
#define HID1E    32
#define NUM_BASIS 20
#define JTILE    256

// Per-node packed data: a[3], b[3], coord[3], pad[3]  (48B, float4-aligned)
__device__ __align__(16) float g_node[NATOMS * 12];

__global__ void node_kernel(
    const float* __restrict__ xs,   const float* __restrict__ xsph,
    const float* __restrict__ coord,
    const float* __restrict__ Wsi1, const float* __restrict__ Wsi2,
    const float* __restrict__ Wsj1, const float* __restrict__ Wsj2,
    const float* __restrict__ Wpi1, const float* __restrict__ Wpi2,
    const float* __restrict__ Wpj1, const float* __restrict__ Wpj2)
{
    int n = blockIdx.x;
    int t = threadIdx.x;
    int lane = t & 31;
    int wid = t >> 5;
    __shared__ float sx[NODE_DIM];
    __shared__ float sv[MUL1E * 3];
    __shared__ float red[4];        // per-warp scalar partials
    __shared__ float soi[3], soj[3];

    sx[t] = xs[n * NODE_DIM + t];
    const float* vp = xsph + n * 480 + 128;   // 1e block [64,3]
    for (int k = t; k < MUL1E * 3; k += 128) sv[k] = vp[k];
    __syncthreads();

    // ---- scalar MLPs: silu(x@W1)@W2.  threads 0..63 -> i-role, 64..127 -> j-role
    {
        const float* W1 = (t < 64) ? Wsi1 : Wsj1;
        const float* W2 = (t < 64) ? Wsi2 : Wsj2;
        int h = t & 63;
        float d = 0.f;
        #pragma unroll 16
        for (int f = 0; f < NODE_DIM; f++) d += sx[f] * W1[f * HIDDEN + h];
        float s = d / (1.f + __expf(-d));     // silu
        float v = s * W2[h];
        #pragma unroll
        for (int off = 16; off > 0; off >>= 1) v += __shfl_down_sync(0xffffffffu, v, off);
        if (lane == 0) red[wid] = v;
    }

    // ---- spherical MLPs: warp 0 -> i-role, warp 1 -> j-role (one lane per hidden h)
    if (t < 64) {
        const float* W1 = (t < 32) ? Wpi1 : Wpj1;
        const float* W2 = (t < 32) ? Wpi2 : Wpj2;
        int h = lane;
        float h0 = 0.f, h1 = 0.f, h2 = 0.f;
        #pragma unroll 16
        for (int m = 0; m < MUL1E; m++) {
            float w = W1[m * HID1E + h];
            h0 += sv[m * 3 + 0] * w;
            h1 += sv[m * 3 + 1] * w;
            h2 += sv[m * 3 + 2] * w;
        }
        h0 *= 0.125f; h1 *= 0.125f; h2 *= 0.125f;   // / sqrt(64)
        float nrm = sqrtf(h0 * h0 + h1 * h1 + h2 * h2);
        float gate = 1.f / (1.f + __expf(-nrm));    // sigmoid(|h|)
        float w2 = W2[h] * gate;
        float o0 = h0 * w2, o1 = h1 * w2, o2 = h2 * w2;
        #pragma unroll
        for (int off = 16; off > 0; off >>= 1) {
            o0 += __shfl_down_sync(0xffffffffu, o0, off);
            o1 += __shfl_down_sync(0xffffffffu, o1, off);
            o2 += __shfl_down_sync(0xffffffffu, o2, off);
        }
        if (lane == 0) {
            float* dst = (t < 32) ? soi : soj;
            dst[0] = o0; dst[1] = o1; dst[2] = o2;
        }
    }
    __syncthreads();

    if (t == 0) {
        const float inv32 = 0.17677669529663689f;   // 1/sqrt(32)
        float fa = (1.f + red[0] + red[1]) * inv32;
        float fb = (1.f + red[2] + red[3]) * inv32;
        float* gp = g_node + n * 12;
        // e3nn (y,z,x) -> (x,y,z) permutation [2,0,1], fold in gate (1+s)
        gp[0] = soi[2] * fa;  gp[1] = soi[0] * fa;  gp[2] = soi[1] * fa;
        gp[3] = soj[2] * fb;  gp[4] = soj[0] * fb;  gp[5] = soj[1] * fb;
        gp[6] = coord[n*3+0]; gp[7] = coord[n*3+1]; gp[8] = coord[n*3+2];
        gp[9] = 0.f; gp[10] = 0.f; gp[11] = 0.f;
    }
}

// out[(i*N+j), p, q] = 0.5 * fc(d_ij) * (a_i[p]*b_j[q] + b_i[p]*a_j[q])
// One block = one i, 256 j's. Stage 9 floats/edge in smem, stream out coalesced.
__global__ __launch_bounds__(JTILE, 4)
void edge_kernel(const float* __restrict__ Wrbf, float* __restrict__ out)
{
    int i  = blockIdx.y;
    int j0 = blockIdx.x * JTILE;
    int t  = threadIdx.x;
    int j  = j0 + t;

    __shared__ __align__(16) float sbuf[JTILE * 9];
    __shared__ float sW[NUM_BASIS];
    __shared__ float si[12];

    if (t < NUM_BASIS) sW[t] = Wrbf[t];
    if (t < 9)         si[t] = g_node[i * 12 + t];
    __syncthreads();

    int nvalid = NATOMS - j0; if (nvalid > JTILE) nvalid = JTILE;

    if (t < nvalid) {
        const float4* np = (const float4*)(g_node + j * 12);
        float4 n0 = np[0], n1 = np[1], n2 = np[2];
        float aj0 = n0.x, aj1 = n0.y, aj2 = n0.z;
        float bj0 = n0.w, bj1 = n1.x, bj2 = n1.y;

        float dx = si[6] - n1.z, dy = si[7] - n1.w, dz = si[8] - n2.x;
        float d = sqrtf(dx * dx + dy * dy + dz * dz);

        const float delta = 5.0f / 19.0f;
        const float coeff = -0.5f / (delta * delta);
        float fc = 0.f;
        #pragma unroll
        for (int k = 0; k < NUM_BASIS; k++) {
            float u = d - (float)k * delta;
            fc += sW[k] * __expf(coeff * u * u);
        }
        float h = 0.5f * fc;

        float ai0 = si[0] * h, ai1 = si[1] * h, ai2 = si[2] * h;
        float bi0 = si[3] * h, bi1 = si[4] * h, bi2 = si[5] * h;

        float* s = sbuf + t * 9;   // stride 9 coprime 32 -> conflict-free
        s[0] = ai0 * bj0 + bi0 * aj0;
        s[1] = ai0 * bj1 + bi0 * aj1;
        s[2] = ai0 * bj2 + bi0 * aj2;
        s[3] = ai1 * bj0 + bi1 * aj0;
        s[4] = ai1 * bj1 + bi1 * aj1;
        s[5] = ai1 * bj2 + bi1 * aj2;
        s[6] = ai2 * bj0 + bi2 * aj0;
        s[7] = ai2 * bj1 + bi2 * aj1;
        s[8] = ai2 * bj2 + bi2 * aj2;
    }
    __syncthreads();

    // Coalesced float4 streaming of nvalid*9 floats (nvalid is 256 or 220,
    // both give nvalid*9 % 4 == 0; base float offset (i*1500+j0)*9 % 4 == 0).
    int total4 = (nvalid * 9) >> 2;
    float4* o4 = (float4*)(out + ((size_t)i * NATOMS + j0) * 9);
    const float4* s4 = (const float4*)sbuf;
    for (int idx = t; idx < total4; idx += JTILE)
        o4[idx] = s4[idx];
}

extern "C" void kernel_launch(void* const* d_in, const int* in_sizes, int n_in,
                              void* d_out, int out_size)
{
    const float* xs    = (const float*)d_in[0];
    const float* xsph  = (const float*)d_in[1];
    const float* coord = (const float*)d_in[2];
    // d_in[3] = fc_edge_index (int32, full graph i-major) — structure fixed, unused
    const float* Wsi1 = (const float*)d_in[4];
    const float* Wsi2 = (const float*)d_in[5];
    const float* Wsj1 = (const float*)d_in[6];
    const float* Wsj2 = (const float*)d_in[7];
    const float* Wpi1 = (const float*)d_in[8];
    const float* Wpi2 = (const float*)d_in[9];
    const float* Wpj1 = (const float*)d_in[10];
    const float* Wpj2 = (const float*)d_in[11];
    const float* Wrbf = (const float*)d_in[12];
    float* out = (float*)d_out;

    node_kernel<<<NATOMS, 128>>>(xs, xsph, coord,
                                 Wsi1, Wsi2, Wsj1, Wsj2,
                                 Wpi1, Wpi2, Wpj1, Wpj2);

    dim3 grid((NATOMS + JTILE - 1) / JTILE, NATOMS);
    edge_kernel<<<grid, JTILE>>>(Wrbf, out);
}